// round 13
// baseline (speedup 1.0000x reference)
#include <cuda_runtime.h>
#include <cuda_fp16.h>
#include <mma.h>
#include <cstddef>
#include <cstdint>

using namespace nvcuda;

#define BB      8
#define HH      56
#define WW      56
#define CC      192
#define HEADS   6
#define HEAD_DIM 32
#define NA      486
#define NAPAD   512
#define HW      3136
#define NROWS   25088
#define SCALE_F 0.17677669529663687f

// -------- scratch (device globals; allocation-free) --------
__device__ __half g_x16[(size_t)NROWS * CC];
__device__ __half g_wv16[CC * CC];
__device__ __half g_wa16[CC * NAPAD];           // Wa padded 486->512, zero-filled
__device__ __half g_wp16[CC * CC];
__device__ __half g_v16[(size_t)NROWS * CC];
__device__ __half g_a16[(size_t)NA * NROWS];    // logits TRANSPOSED [c][row], pre-scaled, fp16
__device__ __half g_o16[(size_t)NROWS * CC];

// ============================================================
// ONE conversion kernel: x, Wv, Wp (fp32->fp16) + Wa (pad 486->512)
// ============================================================
#define XN4   (NROWS * CC / 4)
#define WV4   (CC * CC / 4)
#define WA2   (CC * (NAPAD / 2))
#define CVT_TOT (XN4 + 2 * WV4 + WA2)

__global__ void cvt_all(const float* __restrict__ x,
                        const float* __restrict__ Wv, const float* __restrict__ Wp,
                        const float* __restrict__ Wa,
                        __half* __restrict__ x16,
                        __half* __restrict__ wv16, __half* __restrict__ wp16,
                        __half2* __restrict__ wa16)
{
    int i = blockIdx.x * blockDim.x + threadIdx.x;
    if (i < XN4 + 2 * WV4) {
        const float* s;
        __half* d;
        int j;
        if (i < XN4)            { s = x;  d = x16;  j = i; }
        else if (i < XN4 + WV4) { s = Wv; d = wv16; j = i - XN4; }
        else                    { s = Wp; d = wp16; j = i - XN4 - WV4; }
        float4 v = ((const float4*)s)[j];
        __half2* o = (__half2*)d + j * 2;
        o[0] = __floats2half2_rn(v.x, v.y);
        o[1] = __floats2half2_rn(v.z, v.w);
    } else if (i < CVT_TOT) {
        int j  = i - XN4 - 2 * WV4;
        int r  = j >> 8;
        int c2 = j & 255;
        __half2 hv = __half2half2(__float2half(0.f));
        if (c2 < NA / 2) {
            float2 f = *(const float2*)&Wa[(size_t)r * NA + c2 * 2];
            hv = __floats2half2_rn(f.x, f.y);
        }
        wa16[(size_t)r * (NAPAD / 2) + c2] = hv;
    }
}

// ============================================================
// FP16 GEMM, 3-stage cp.async, block 128x64, warp 32x32 (4x2).
// ============================================================
#define BM 128
#define BN 64
#define KB 32
#define NT (CC / KB)
#define A_LDH 40
#define B_LDH 72
#define C_LD  68
#define A_SZ (BM * A_LDH)
#define B_SZ (KB * B_LDH)
#define STG_H (A_SZ + B_SZ)
#define SMEM_BYTES (3 * STG_H * 2 > BM * C_LD * 4 ? 3 * STG_H * 2 : BM * C_LD * 4)

__device__ __forceinline__ void cpa16(void* dst, const void* src)
{
    uint32_t d = (uint32_t)__cvta_generic_to_shared(dst);
    asm volatile("cp.async.cg.shared.global [%0], [%1], 16;\n" :: "r"(d), "l"(src));
}

template<int NCPAD, int NC, bool HASB, bool TRANSC, bool OUT16>
__global__ void __launch_bounds__(256) gemm_h(const __half* __restrict__ A,
                                              const __half* __restrict__ Bw,
                                              const float* __restrict__ bias,
                                              void* __restrict__ CoutV)
{
    __shared__ __align__(16) unsigned char smraw[SMEM_BYTES];
    __half* sh = (__half*)smraw;
    float* smf = (float*)smraw;

    const int tid = threadIdx.x;
    const int wid = tid >> 5;
    const int wm  = wid >> 1;
    const int wn  = wid & 1;
    const int rowBase = blockIdx.y * BM;
    const int colBase = blockIdx.x * BN;

    auto loadStage = [&](int s, int kt) {
        __half* As = sh + s * STG_H;
        __half* Bs = As + A_SZ;
#pragma unroll
        for (int p = 0; p < 2; p++) {
            int c = tid + p * 256;
            int r = c >> 2, off = (c & 3) << 3;
            cpa16(&As[r * A_LDH + off], &A[(size_t)(rowBase + r) * CC + kt + off]);
        }
        {
            int k = tid >> 3, off = (tid & 7) << 3;
            cpa16(&Bs[k * B_LDH + off], &Bw[(size_t)(kt + k) * NCPAD + colBase + off]);
        }
        asm volatile("cp.async.commit_group;\n");
    };

    wmma::fragment<wmma::accumulator, 16, 16, 16, float> cf[2][2];
#pragma unroll
    for (int i = 0; i < 2; i++)
#pragma unroll
        for (int j = 0; j < 2; j++) wmma::fill_fragment(cf[i][j], 0.f);

    loadStage(0, 0);
    loadStage(1, KB);

#pragma unroll
    for (int t = 0; t < NT; t++) {
        if (t + 2 < NT) {
            loadStage((t + 2) % 3, (t + 2) * KB);
            asm volatile("cp.async.wait_group 2;\n");
        } else if (t + 1 < NT) {
            asm volatile("cp.async.wait_group 1;\n");
        } else {
            asm volatile("cp.async.wait_group 0;\n");
        }
        __syncthreads();

        const __half* As = sh + (t % 3) * STG_H;
        const __half* Bs = As + A_SZ;
#pragma unroll
        for (int kk = 0; kk < KB / 16; kk++) {
            wmma::fragment<wmma::matrix_b, 16, 16, 16, __half, wmma::row_major> bf[2];
            wmma::fragment<wmma::matrix_a, 16, 16, 16, __half, wmma::row_major> af[2];
#pragma unroll
            for (int j = 0; j < 2; j++)
                wmma::load_matrix_sync(bf[j], &Bs[(kk * 16) * B_LDH + wn * 32 + j * 16], B_LDH);
#pragma unroll
            for (int i = 0; i < 2; i++)
                wmma::load_matrix_sync(af[i], &As[(wm * 32 + i * 16) * A_LDH + kk * 16], A_LDH);
#pragma unroll
            for (int i = 0; i < 2; i++)
#pragma unroll
                for (int j = 0; j < 2; j++)
                    wmma::mma_sync(cf[i][j], af[i], bf[j], cf[i][j]);
        }
        __syncthreads();
    }

    float* Cs = smf;                           // [BM][C_LD]
#pragma unroll
    for (int i = 0; i < 2; i++)
#pragma unroll
        for (int j = 0; j < 2; j++)
            wmma::store_matrix_sync(&Cs[(wm * 32 + i * 16) * C_LD + wn * 32 + j * 16],
                                    cf[i][j], C_LD, wmma::mem_row_major);
    __syncthreads();

    if (OUT16) {
        __half* Cout = (__half*)CoutV;
#pragma unroll
        for (int p = 0; p < (BM * BN) / 512; p++) {
            int idx = tid + p * 256;
            int r  = idx >> 5;
            int c2 = (idx & 31) << 1;
            __half2 hv = __floats2half2_rn(Cs[r * C_LD + c2], Cs[r * C_LD + c2 + 1]);
            *(__half2*)&Cout[(size_t)(rowBase + r) * NC + colBase + c2] = hv;
        }
    } else if (TRANSC) {
        __half* Cout = (__half*)CoutV;
#pragma unroll
        for (int p = 0; p < (BM * BN) / 512; p++) {
            int idx = tid + p * 256;
            int c  = idx >> 6;
            int r2 = idx & 63;
            int gc = colBase + c;
            if (gc < NC) {
                float b = bias[gc];
                float v0 = (Cs[(2 * r2 + 0) * C_LD + c] + b) * SCALE_F;
                float v1 = (Cs[(2 * r2 + 1) * C_LD + c] + b) * SCALE_F;
                *(__half2*)&Cout[(size_t)gc * NROWS + rowBase + 2 * r2] =
                    __floats2half2_rn(v0, v1);
            }
        }
    } else {
        float* Cout = (float*)CoutV;
#pragma unroll
        for (int p = 0; p < (BM * BN) / 256; p++) {
            int idx = tid + p * 256;
            int r = idx >> 6;
            int c = idx & 63;
            int gc = colBase + c;
            if (gc < NC) {
                float v = Cs[r * C_LD + c];
                if (HASB) v += bias[gc];
                Cout[(size_t)(rowBase + r) * NC + gc] = v;
            }
        }
    }
}

// ============================================================
// Fused softmax + attention-apply + fold.
// 14x14 tiles (56 = 4*14, zero idle boundary threads), 224 threads,
// static 46.7KB smem -> 4 CTAs/SM. Gather uses packed fma.rn.f32x2
// (full fp32 precision, half the FMA instructions).
// ============================================================
#define TS  14            // tile size
#define HALO 18           // TS + 4
#define VST 36            // smem floats per pixel (144B = odd mult of 16B)
#define NPIX (TS * TS)    // 196 active threads
#define NTHR 224

__device__ __forceinline__ void fma_x2(unsigned long long& d,
                                       unsigned long long a,
                                       unsigned long long b)
{
    asm("fma.rn.f32x2 %0, %1, %2, %0;" : "+l"(d) : "l"(a), "l"(b));
}

__global__ void __launch_bounds__(NTHR, 4) agg_kernel(const __half* __restrict__ a,
                                                      const __half* __restrict__ v,
                                                      __half* __restrict__ o)
{
    __shared__ float vsm[HALO * HALO * VST];   // 46.66 KB (static, < 48KB)

    const int bh = blockIdx.z;
    const int b  = bh / HEADS;
    const int h  = bh - b * HEADS;
    const int ty0 = blockIdx.y * TS;
    const int tx0 = blockIdx.x * TS;
    const int tid = threadIdx.x;

    // cooperative load of v tile+halo (fp16 -> fp32 smem), zeros outside image
    for (int i = tid; i < HALO * HALO * 4; i += NTHR) {
        const int p = i >> 2;
        const int q = (i & 3) << 3;
        const int sy = p / HALO;
        const int sx = p - sy * HALO;
        const int gy = ty0 + sy - 2;
        const int gx = tx0 + sx - 2;
        float4 raw = make_float4(0.f, 0.f, 0.f, 0.f);
        if (gy >= 0 && gy < HH && gx >= 0 && gx < WW)
            raw = *(const float4*)&v[((size_t)(b * HW + gy * WW + gx)) * CC + h * HEAD_DIM + q];
        const __half2* hp = (const __half2*)&raw;
        float2 f0 = __half22float2(hp[0]);
        float2 f1 = __half22float2(hp[1]);
        float2 f2 = __half22float2(hp[2]);
        float2 f3 = __half22float2(hp[3]);
        float4* d = (float4*)&vsm[p * VST + q];
        d[0] = make_float4(f0.x, f0.y, f1.x, f1.y);
        d[1] = make_float4(f2.x, f2.y, f3.x, f3.y);
    }
    __syncthreads();

    if (tid >= NPIX) return;     // no further barriers
    const int py = tid / TS;
    const int px = tid - py * TS;
    const int gy = ty0 + py;
    const int gx = tx0 + px;

    // reduce 81 softmaxed logits into 25 positional weights
    float w[25];
#pragma unroll
    for (int i = 0; i < 25; i++) w[i] = 0.f;

#pragma unroll
    for (int i = 0; i < 3; i++) {
#pragma unroll
        for (int j = 0; j < 3; j++) {
            const int cy = gy + 1 - i;
            const int cx = gx + 1 - j;
            if (cy < 0 || cy >= HH || cx < 0 || cx >= WW) continue;
            const size_t row = (size_t)(b * HW + cy * WW + cx);
            const __half* ap = a + (size_t)(h * 81 + (i * 3 + j) * 9) * NROWS + row;
            float e[9];
            float s = 0.f;
            // logits are pre-scaled, |arg| <~ 1.5: exp safe without max-shift
#pragma unroll
            for (int l = 0; l < 9; l++) {
                e[l] = __expf(__half2float(ap[(size_t)l * NROWS]));
                s += e[l];
            }
            const float inv = 1.f / s;
#pragma unroll
            for (int li = 0; li < 3; li++) {
#pragma unroll
                for (int lj = 0; lj < 3; lj++) {
                    w[(li - i + 2) * 5 + (lj - j + 2)] += e[li * 3 + lj] * inv;
                }
            }
        }
    }

    // weighted 5x5 gather: packed f32x2 FMAs (fp32 precision, half the instrs)
    unsigned long long acc2[HEAD_DIM / 2];
#pragma unroll
    for (int u = 0; u < HEAD_DIM / 2; u++) acc2[u] = 0ull;

#pragma unroll
    for (int dy = 0; dy < 5; dy++) {
#pragma unroll
        for (int dx = 0; dx < 5; dx++) {
            const float wv = w[dy * 5 + dx];
            unsigned long long wp;
            asm("mov.b64 %0, {%1, %1};" : "=l"(wp) : "f"(wv));
            const ulonglong2* vp =
                (const ulonglong2*)&vsm[((py + dy) * HALO + (px + dx)) * VST];
#pragma unroll
            for (int u = 0; u < 8; u++) {
                ulonglong2 t = vp[u];
                fma_x2(acc2[2 * u + 0], t.x, wp);
                fma_x2(acc2[2 * u + 1], t.y, wp);
            }
        }
    }

    __half2* op = (__half2*)(o + ((size_t)(b * HW + gy * WW + gx)) * CC + h * HEAD_DIM);
#pragma unroll
    for (int u = 0; u < HEAD_DIM / 2; u++) {
        float lo = __uint_as_float((unsigned)(acc2[u] & 0xffffffffu));
        float hi = __uint_as_float((unsigned)(acc2[u] >> 32));
        op[u] = __floats2half2_rn(lo, hi);
    }
}

// ============================================================
extern "C" void kernel_launch(void* const* d_in, const int* in_sizes, int n_in,
                              void* d_out, int out_size)
{
    const float* x  = (const float*)d_in[0];
    const float* Wv = (const float*)d_in[1];
    const float* Wa = (const float*)d_in[2];
    const float* ba = (const float*)d_in[3];
    const float* Wp = (const float*)d_in[4];
    const float* bp = (const float*)d_in[5];
    float* out = (float*)d_out;

    __half *x16, *wv16, *wa16, *wp16, *v16, *a16, *o16;
    cudaGetSymbolAddress((void**)&x16,  g_x16);
    cudaGetSymbolAddress((void**)&wv16, g_wv16);
    cudaGetSymbolAddress((void**)&wa16, g_wa16);
    cudaGetSymbolAddress((void**)&wp16, g_wp16);
    cudaGetSymbolAddress((void**)&v16,  g_v16);
    cudaGetSymbolAddress((void**)&a16,  g_a16);
    cudaGetSymbolAddress((void**)&o16,  g_o16);

    // 0) all conversions in one launch
    cvt_all<<<(CVT_TOT + 255) / 256, 256>>>(x, Wv, Wp, Wa, x16, wv16, wp16, (__half2*)wa16);

    // 1) v16 = x @ Wv   (fp16 out)
    gemm_h<192, 192, false, false, true>
        <<<dim3(3, NROWS / BM), 256>>>(x16, wv16, nullptr, v16);
    // 2) a16_t = transpose((x @ Wa + ba) * SCALE)   (fp16, column-major)
    gemm_h<NAPAD, NA, true, true, false>
        <<<dim3(NAPAD / BN, NROWS / BM), 256>>>(x16, wa16, ba, a16);
    // 3) fused softmax + attention-apply + fold  (o fp16)
    agg_kernel<<<dim3(4, 4, BB * HEADS), NTHR>>>(a16, v16, o16);
    // 4) out = o @ Wp + bp   (fp32 out)
    gemm_h<192, 192, true, false, false>
        <<<dim3(3, NROWS / BM), 256>>>(o16, wp16, bp, out);
}

// round 14
// speedup vs baseline: 1.0197x; 1.0197x over previous
#include <cuda_runtime.h>
#include <cuda_fp16.h>
#include <mma.h>
#include <cstddef>
#include <cstdint>

using namespace nvcuda;

#define BB      8
#define HH      56
#define WW      56
#define CC      192
#define HEADS   6
#define HEAD_DIM 32
#define NA      486
#define NAPAD   512
#define HW      3136
#define NROWS   25088
#define SCALE_F 0.17677669529663687f

// -------- scratch (device globals; allocation-free) --------
__device__ __half g_x16[(size_t)NROWS * CC];
__device__ __half g_wv16[CC * CC];
__device__ __half g_wa16[CC * NAPAD];           // Wa padded 486->512, zero-filled
__device__ __half g_wp16[CC * CC];
__device__ __half g_v16[(size_t)NROWS * CC];
__device__ __half g_e16[(size_t)NA * NROWS];    // EXP'ED logits TRANSPOSED [c][row], fp16
__device__ __half g_o16[(size_t)NROWS * CC];

// ============================================================
// ONE conversion kernel: x, Wv, Wp (fp32->fp16) + Wa (pad 486->512)
// ============================================================
#define XN4   (NROWS * CC / 4)
#define WV4   (CC * CC / 4)
#define WA2   (CC * (NAPAD / 2))
#define CVT_TOT (XN4 + 2 * WV4 + WA2)

__global__ void cvt_all(const float* __restrict__ x,
                        const float* __restrict__ Wv, const float* __restrict__ Wp,
                        const float* __restrict__ Wa,
                        __half* __restrict__ x16,
                        __half* __restrict__ wv16, __half* __restrict__ wp16,
                        __half2* __restrict__ wa16)
{
    int i = blockIdx.x * blockDim.x + threadIdx.x;
    if (i < XN4 + 2 * WV4) {
        const float* s;
        __half* d;
        int j;
        if (i < XN4)            { s = x;  d = x16;  j = i; }
        else if (i < XN4 + WV4) { s = Wv; d = wv16; j = i - XN4; }
        else                    { s = Wp; d = wp16; j = i - XN4 - WV4; }
        float4 v = ((const float4*)s)[j];
        __half2* o = (__half2*)d + j * 2;
        o[0] = __floats2half2_rn(v.x, v.y);
        o[1] = __floats2half2_rn(v.z, v.w);
    } else if (i < CVT_TOT) {
        int j  = i - XN4 - 2 * WV4;
        int r  = j >> 8;
        int c2 = j & 255;
        __half2 hv = __half2half2(__float2half(0.f));
        if (c2 < NA / 2) {
            float2 f = *(const float2*)&Wa[(size_t)r * NA + c2 * 2];
            hv = __floats2half2_rn(f.x, f.y);
        }
        wa16[(size_t)r * (NAPAD / 2) + c2] = hv;
    }
}

// ============================================================
// FP16 GEMM, 3-stage cp.async, block 128x64, warp 32x32 (4x2).
// TRANSC (logits path): store exp((acc+bias)*SCALE) fp16 column-major
// [c][row] — softmax exp runs HERE on the idle MUFU pipe, overlapped
// with other CTAs' tensor mainloops.
// ============================================================
#define BM 128
#define BN 64
#define KB 32
#define NT (CC / KB)
#define A_LDH 40
#define B_LDH 72
#define C_LD  68
#define A_SZ (BM * A_LDH)
#define B_SZ (KB * B_LDH)
#define STG_H (A_SZ + B_SZ)
#define SMEM_BYTES (3 * STG_H * 2 > BM * C_LD * 4 ? 3 * STG_H * 2 : BM * C_LD * 4)

__device__ __forceinline__ void cpa16(void* dst, const void* src)
{
    uint32_t d = (uint32_t)__cvta_generic_to_shared(dst);
    asm volatile("cp.async.cg.shared.global [%0], [%1], 16;\n" :: "r"(d), "l"(src));
}

template<int NCPAD, int NC, bool HASB, bool TRANSC, bool OUT16>
__global__ void __launch_bounds__(256) gemm_h(const __half* __restrict__ A,
                                              const __half* __restrict__ Bw,
                                              const float* __restrict__ bias,
                                              void* __restrict__ CoutV)
{
    __shared__ __align__(16) unsigned char smraw[SMEM_BYTES];
    __half* sh = (__half*)smraw;
    float* smf = (float*)smraw;

    const int tid = threadIdx.x;
    const int wid = tid >> 5;
    const int wm  = wid >> 1;
    const int wn  = wid & 1;
    const int rowBase = blockIdx.y * BM;
    const int colBase = blockIdx.x * BN;

    auto loadStage = [&](int s, int kt) {
        __half* As = sh + s * STG_H;
        __half* Bs = As + A_SZ;
#pragma unroll
        for (int p = 0; p < 2; p++) {
            int c = tid + p * 256;
            int r = c >> 2, off = (c & 3) << 3;
            cpa16(&As[r * A_LDH + off], &A[(size_t)(rowBase + r) * CC + kt + off]);
        }
        {
            int k = tid >> 3, off = (tid & 7) << 3;
            cpa16(&Bs[k * B_LDH + off], &Bw[(size_t)(kt + k) * NCPAD + colBase + off]);
        }
        asm volatile("cp.async.commit_group;\n");
    };

    wmma::fragment<wmma::accumulator, 16, 16, 16, float> cf[2][2];
#pragma unroll
    for (int i = 0; i < 2; i++)
#pragma unroll
        for (int j = 0; j < 2; j++) wmma::fill_fragment(cf[i][j], 0.f);

    loadStage(0, 0);
    loadStage(1, KB);

#pragma unroll
    for (int t = 0; t < NT; t++) {
        if (t + 2 < NT) {
            loadStage((t + 2) % 3, (t + 2) * KB);
            asm volatile("cp.async.wait_group 2;\n");
        } else if (t + 1 < NT) {
            asm volatile("cp.async.wait_group 1;\n");
        } else {
            asm volatile("cp.async.wait_group 0;\n");
        }
        __syncthreads();

        const __half* As = sh + (t % 3) * STG_H;
        const __half* Bs = As + A_SZ;
#pragma unroll
        for (int kk = 0; kk < KB / 16; kk++) {
            wmma::fragment<wmma::matrix_b, 16, 16, 16, __half, wmma::row_major> bf[2];
            wmma::fragment<wmma::matrix_a, 16, 16, 16, __half, wmma::row_major> af[2];
#pragma unroll
            for (int j = 0; j < 2; j++)
                wmma::load_matrix_sync(bf[j], &Bs[(kk * 16) * B_LDH + wn * 32 + j * 16], B_LDH);
#pragma unroll
            for (int i = 0; i < 2; i++)
                wmma::load_matrix_sync(af[i], &As[(wm * 32 + i * 16) * A_LDH + kk * 16], A_LDH);
#pragma unroll
            for (int i = 0; i < 2; i++)
#pragma unroll
                for (int j = 0; j < 2; j++)
                    wmma::mma_sync(cf[i][j], af[i], bf[j], cf[i][j]);
        }
        __syncthreads();
    }

    float* Cs = smf;                           // [BM][C_LD]
#pragma unroll
    for (int i = 0; i < 2; i++)
#pragma unroll
        for (int j = 0; j < 2; j++)
            wmma::store_matrix_sync(&Cs[(wm * 32 + i * 16) * C_LD + wn * 32 + j * 16],
                                    cf[i][j], C_LD, wmma::mem_row_major);
    __syncthreads();

    if (OUT16) {
        __half* Cout = (__half*)CoutV;
#pragma unroll
        for (int p = 0; p < (BM * BN) / 512; p++) {
            int idx = tid + p * 256;
            int r  = idx >> 5;
            int c2 = (idx & 31) << 1;
            __half2 hv = __floats2half2_rn(Cs[r * C_LD + c2], Cs[r * C_LD + c2 + 1]);
            *(__half2*)&Cout[(size_t)(rowBase + r) * NC + colBase + c2] = hv;
        }
    } else if (TRANSC) {
        // pre-exp'ed softmax numerators, fp16 column-major [c][row]
        __half* Cout = (__half*)CoutV;
#pragma unroll
        for (int p = 0; p < (BM * BN) / 512; p++) {
            int idx = tid + p * 256;
            int c  = idx >> 6;
            int r2 = idx & 63;
            int gc = colBase + c;
            if (gc < NC) {
                float b = bias[gc];
                float v0 = __expf((Cs[(2 * r2 + 0) * C_LD + c] + b) * SCALE_F);
                float v1 = __expf((Cs[(2 * r2 + 1) * C_LD + c] + b) * SCALE_F);
                *(__half2*)&Cout[(size_t)gc * NROWS + rowBase + 2 * r2] =
                    __floats2half2_rn(v0, v1);
            }
        }
    } else {
        float* Cout = (float*)CoutV;
#pragma unroll
        for (int p = 0; p < (BM * BN) / 256; p++) {
            int idx = tid + p * 256;
            int r = idx >> 6;
            int c = idx & 63;
            int gc = colBase + c;
            if (gc < NC) {
                float v = Cs[r * C_LD + c];
                if (HASB) v += bias[gc];
                Cout[(size_t)(rowBase + r) * NC + gc] = v;
            }
        }
    }
}

// ============================================================
// Fused softmax-normalize + attention-apply + fold.
// e: fp16 PRE-EXP'ED logits TRANSPOSED [c][row] (coalesced loads).
// Per group: sum 9, reciprocal, accumulate — no exp, no max here.
// v: fp16 -> fp32 smem (stride 36 floats); float4 gather (R12 proven).
// ============================================================
#define VST 36

__global__ void agg_kernel(const __half* __restrict__ e16,
                           const __half* __restrict__ v,
                           __half* __restrict__ o)
{
    extern __shared__ float vsm[];

    const int bh = blockIdx.z;
    const int b  = bh / HEADS;
    const int h  = bh - b * HEADS;
    const int ty0 = blockIdx.y * 16;
    const int tx0 = blockIdx.x * 16;
    const int tid = threadIdx.x;

    for (int i = tid; i < 20 * 20 * 4; i += 256) {
        const int p = i >> 2;
        const int q = (i & 3) << 3;
        const int sy = p / 20;
        const int sx = p - sy * 20;
        const int gy = ty0 + sy - 2;
        const int gx = tx0 + sx - 2;
        float4 raw = make_float4(0.f, 0.f, 0.f, 0.f);
        if (gy >= 0 && gy < HH && gx >= 0 && gx < WW)
            raw = *(const float4*)&v[((size_t)(b * HW + gy * WW + gx)) * CC + h * HEAD_DIM + q];
        const __half2* hp = (const __half2*)&raw;
        float2 f0 = __half22float2(hp[0]);
        float2 f1 = __half22float2(hp[1]);
        float2 f2 = __half22float2(hp[2]);
        float2 f3 = __half22float2(hp[3]);
        float4* d = (float4*)&vsm[p * VST + q];
        d[0] = make_float4(f0.x, f0.y, f1.x, f1.y);
        d[1] = make_float4(f2.x, f2.y, f3.x, f3.y);
    }
    __syncthreads();

    const int px = tid & 15;
    const int py = tid >> 4;
    const int gy = ty0 + py;
    const int gx = tx0 + px;
    if (gy >= HH || gx >= WW) return;

    float w[25];
#pragma unroll
    for (int i = 0; i < 25; i++) w[i] = 0.f;

#pragma unroll
    for (int i = 0; i < 3; i++) {
#pragma unroll
        for (int j = 0; j < 3; j++) {
            const int cy = gy + 1 - i;
            const int cx = gx + 1 - j;
            if (cy < 0 || cy >= HH || cx < 0 || cx >= WW) continue;
            const size_t row = (size_t)(b * HW + cy * WW + cx);
            const __half* ap = e16 + (size_t)(h * 81 + (i * 3 + j) * 9) * NROWS + row;
            float e[9];
            float s = 0.f;
#pragma unroll
            for (int l = 0; l < 9; l++) {
                e[l] = __half2float(ap[(size_t)l * NROWS]);
                s += e[l];
            }
            const float inv = 1.f / s;
#pragma unroll
            for (int li = 0; li < 3; li++) {
#pragma unroll
                for (int lj = 0; lj < 3; lj++) {
                    w[(li - i + 2) * 5 + (lj - j + 2)] += e[li * 3 + lj] * inv;
                }
            }
        }
    }

    float4 acc[HEAD_DIM / 4];
#pragma unroll
    for (int u = 0; u < HEAD_DIM / 4; u++) acc[u] = make_float4(0.f, 0.f, 0.f, 0.f);

#pragma unroll
    for (int dy = 0; dy < 5; dy++) {
#pragma unroll
        for (int dx = 0; dx < 5; dx++) {
            const float wv = w[dy * 5 + dx];
            const float4* vp = (const float4*)&vsm[((py + dy) * 20 + (px + dx)) * VST];
#pragma unroll
            for (int u = 0; u < HEAD_DIM / 4; u++) {
                float4 t = vp[u];
                acc[u].x += wv * t.x;
                acc[u].y += wv * t.y;
                acc[u].z += wv * t.z;
                acc[u].w += wv * t.w;
            }
        }
    }

    __half2* op = (__half2*)(o + ((size_t)(b * HW + gy * WW + gx)) * CC + h * HEAD_DIM);
#pragma unroll
    for (int u = 0; u < HEAD_DIM / 4; u++) {
        op[u * 2 + 0] = __floats2half2_rn(acc[u].x, acc[u].y);
        op[u * 2 + 1] = __floats2half2_rn(acc[u].z, acc[u].w);
    }
}

// ============================================================
extern "C" void kernel_launch(void* const* d_in, const int* in_sizes, int n_in,
                              void* d_out, int out_size)
{
    const float* x  = (const float*)d_in[0];
    const float* Wv = (const float*)d_in[1];
    const float* Wa = (const float*)d_in[2];
    const float* ba = (const float*)d_in[3];
    const float* Wp = (const float*)d_in[4];
    const float* bp = (const float*)d_in[5];
    float* out = (float*)d_out;

    __half *x16, *wv16, *wa16, *wp16, *v16, *e16, *o16;
    cudaGetSymbolAddress((void**)&x16,  g_x16);
    cudaGetSymbolAddress((void**)&wv16, g_wv16);
    cudaGetSymbolAddress((void**)&wa16, g_wa16);
    cudaGetSymbolAddress((void**)&wp16, g_wp16);
    cudaGetSymbolAddress((void**)&v16,  g_v16);
    cudaGetSymbolAddress((void**)&e16,  g_e16);
    cudaGetSymbolAddress((void**)&o16,  g_o16);

    const int smem_agg = 20 * 20 * VST * sizeof(float);   // 57.6 KB
    cudaFuncSetAttribute(agg_kernel, cudaFuncAttributeMaxDynamicSharedMemorySize, smem_agg);

    // 0) all conversions in one launch
    cvt_all<<<(CVT_TOT + 255) / 256, 256>>>(x, Wv, Wp, Wa, x16, wv16, wp16, (__half2*)wa16);

    // 1) v16 = x @ Wv   (fp16 out)
    gemm_h<192, 192, false, false, true>
        <<<dim3(3, NROWS / BM), 256>>>(x16, wv16, nullptr, v16);
    // 2) e16_t = exp(transpose((x @ Wa + ba) * SCALE))   (fp16, column-major)
    gemm_h<NAPAD, NA, true, true, false>
        <<<dim3(NAPAD / BN, NROWS / BM), 256>>>(x16, wa16, ba, e16);
    // 3) fused softmax-normalize + attention-apply + fold  (o fp16)
    agg_kernel<<<dim3(4, 4, BB * HEADS), 256, smem_agg>>>(e16, v16, o16);
    // 4) out = o @ Wp + bp   (fp32 out)
    gemm_h<192, 192, true, false, false>
        <<<dim3(3, NROWS / BM), 256>>>(o16, wp16, bp, out);
}

// round 15
// speedup vs baseline: 1.1366x; 1.1147x over previous
#include <cuda_runtime.h>
#include <cuda_fp16.h>
#include <mma.h>
#include <cstddef>
#include <cstdint>

using namespace nvcuda;

#define BB      8
#define HH      56
#define WW      56
#define CC      192
#define HEADS   6
#define HEAD_DIM 32
#define NA      486
#define NAPAD   512
#define HW      3136
#define NROWS   25088
#define SCALE_F 0.17677669529663687f

// -------- scratch (device globals; allocation-free) --------
__device__ __half g_x16[(size_t)NROWS * CC];
__device__ __half g_wv16[CC * CC];
__device__ __half g_wa16[CC * NAPAD];           // Wa padded 486->512, zero-filled
__device__ __half g_wp16[CC * CC];
__device__ __half g_v16[(size_t)NROWS * CC];
__device__ __half g_a16[(size_t)NA * NROWS];    // logits TRANSPOSED [c][row], pre-scaled, fp16
__device__ __half g_o16[(size_t)NROWS * CC];

// ============================================================
// ONE conversion kernel: x, Wv, Wp (fp32->fp16) + Wa (pad 486->512)
// ============================================================
#define XN4   (NROWS * CC / 4)
#define WV4   (CC * CC / 4)
#define WA2   (CC * (NAPAD / 2))
#define CVT_TOT (XN4 + 2 * WV4 + WA2)

__global__ void cvt_all(const float* __restrict__ x,
                        const float* __restrict__ Wv, const float* __restrict__ Wp,
                        const float* __restrict__ Wa,
                        __half* __restrict__ x16,
                        __half* __restrict__ wv16, __half* __restrict__ wp16,
                        __half2* __restrict__ wa16)
{
    int i = blockIdx.x * blockDim.x + threadIdx.x;
    if (i < XN4 + 2 * WV4) {
        const float* s;
        __half* d;
        int j;
        if (i < XN4)            { s = x;  d = x16;  j = i; }
        else if (i < XN4 + WV4) { s = Wv; d = wv16; j = i - XN4; }
        else                    { s = Wp; d = wp16; j = i - XN4 - WV4; }
        float4 v = ((const float4*)s)[j];
        __half2* o = (__half2*)d + j * 2;
        o[0] = __floats2half2_rn(v.x, v.y);
        o[1] = __floats2half2_rn(v.z, v.w);
    } else if (i < CVT_TOT) {
        int j  = i - XN4 - 2 * WV4;
        int r  = j >> 8;
        int c2 = j & 255;
        __half2 hv = __half2half2(__float2half(0.f));
        if (c2 < NA / 2) {
            float2 f = *(const float2*)&Wa[(size_t)r * NA + c2 * 2];
            hv = __floats2half2_rn(f.x, f.y);
        }
        wa16[(size_t)r * (NAPAD / 2) + c2] = hv;
    }
}

// ============================================================
// FP16 GEMM, 3-stage cp.async, block 128x64, warp 32x32 (4x2).
// ============================================================
#define BM 128
#define BN 64
#define KB 32
#define NT (CC / KB)
#define A_LDH 40
#define B_LDH 72
#define C_LD  68
#define A_SZ (BM * A_LDH)
#define B_SZ (KB * B_LDH)
#define STG_H (A_SZ + B_SZ)
#define SMEM_BYTES (3 * STG_H * 2 > BM * C_LD * 4 ? 3 * STG_H * 2 : BM * C_LD * 4)

__device__ __forceinline__ void cpa16(void* dst, const void* src)
{
    uint32_t d = (uint32_t)__cvta_generic_to_shared(dst);
    asm volatile("cp.async.cg.shared.global [%0], [%1], 16;\n" :: "r"(d), "l"(src));
}

template<int NCPAD, int NC, bool HASB, bool TRANSC, bool OUT16>
__global__ void __launch_bounds__(256) gemm_h(const __half* __restrict__ A,
                                              const __half* __restrict__ Bw,
                                              const float* __restrict__ bias,
                                              void* __restrict__ CoutV)
{
    __shared__ __align__(16) unsigned char smraw[SMEM_BYTES];
    __half* sh = (__half*)smraw;
    float* smf = (float*)smraw;

    const int tid = threadIdx.x;
    const int wid = tid >> 5;
    const int wm  = wid >> 1;
    const int wn  = wid & 1;
    const int rowBase = blockIdx.y * BM;
    const int colBase = blockIdx.x * BN;

    auto loadStage = [&](int s, int kt) {
        __half* As = sh + s * STG_H;
        __half* Bs = As + A_SZ;
#pragma unroll
        for (int p = 0; p < 2; p++) {
            int c = tid + p * 256;
            int r = c >> 2, off = (c & 3) << 3;
            cpa16(&As[r * A_LDH + off], &A[(size_t)(rowBase + r) * CC + kt + off]);
        }
        {
            int k = tid >> 3, off = (tid & 7) << 3;
            cpa16(&Bs[k * B_LDH + off], &Bw[(size_t)(kt + k) * NCPAD + colBase + off]);
        }
        asm volatile("cp.async.commit_group;\n");
    };

    wmma::fragment<wmma::accumulator, 16, 16, 16, float> cf[2][2];
#pragma unroll
    for (int i = 0; i < 2; i++)
#pragma unroll
        for (int j = 0; j < 2; j++) wmma::fill_fragment(cf[i][j], 0.f);

    loadStage(0, 0);
    loadStage(1, KB);

#pragma unroll
    for (int t = 0; t < NT; t++) {
        if (t + 2 < NT) {
            loadStage((t + 2) % 3, (t + 2) * KB);
            asm volatile("cp.async.wait_group 2;\n");
        } else if (t + 1 < NT) {
            asm volatile("cp.async.wait_group 1;\n");
        } else {
            asm volatile("cp.async.wait_group 0;\n");
        }
        __syncthreads();

        const __half* As = sh + (t % 3) * STG_H;
        const __half* Bs = As + A_SZ;
#pragma unroll
        for (int kk = 0; kk < KB / 16; kk++) {
            wmma::fragment<wmma::matrix_b, 16, 16, 16, __half, wmma::row_major> bf[2];
            wmma::fragment<wmma::matrix_a, 16, 16, 16, __half, wmma::row_major> af[2];
#pragma unroll
            for (int j = 0; j < 2; j++)
                wmma::load_matrix_sync(bf[j], &Bs[(kk * 16) * B_LDH + wn * 32 + j * 16], B_LDH);
#pragma unroll
            for (int i = 0; i < 2; i++)
                wmma::load_matrix_sync(af[i], &As[(wm * 32 + i * 16) * A_LDH + kk * 16], A_LDH);
#pragma unroll
            for (int i = 0; i < 2; i++)
#pragma unroll
                for (int j = 0; j < 2; j++)
                    wmma::mma_sync(cf[i][j], af[i], bf[j], cf[i][j]);
        }
        __syncthreads();
    }

    float* Cs = smf;                           // [BM][C_LD]
#pragma unroll
    for (int i = 0; i < 2; i++)
#pragma unroll
        for (int j = 0; j < 2; j++)
            wmma::store_matrix_sync(&Cs[(wm * 32 + i * 16) * C_LD + wn * 32 + j * 16],
                                    cf[i][j], C_LD, wmma::mem_row_major);
    __syncthreads();

    if (OUT16) {
        __half* Cout = (__half*)CoutV;
#pragma unroll
        for (int p = 0; p < (BM * BN) / 512; p++) {
            int idx = tid + p * 256;
            int r  = idx >> 5;
            int c2 = (idx & 31) << 1;
            __half2 hv = __floats2half2_rn(Cs[r * C_LD + c2], Cs[r * C_LD + c2 + 1]);
            *(__half2*)&Cout[(size_t)(rowBase + r) * NC + colBase + c2] = hv;
        }
    } else if (TRANSC) {
        // pre-scaled logits, fp16 column-major [c][row]
        __half* Cout = (__half*)CoutV;
#pragma unroll
        for (int p = 0; p < (BM * BN) / 512; p++) {
            int idx = tid + p * 256;
            int c  = idx >> 6;
            int r2 = idx & 63;
            int gc = colBase + c;
            if (gc < NC) {
                float b = bias[gc];
                float v0 = (Cs[(2 * r2 + 0) * C_LD + c] + b) * SCALE_F;
                float v1 = (Cs[(2 * r2 + 1) * C_LD + c] + b) * SCALE_F;
                *(__half2*)&Cout[(size_t)gc * NROWS + rowBase + 2 * r2] =
                    __floats2half2_rn(v0, v1);
            }
        }
    } else {
        float* Cout = (float*)CoutV;
#pragma unroll
        for (int p = 0; p < (BM * BN) / 256; p++) {
            int idx = tid + p * 256;
            int r = idx >> 6;
            int c = idx & 63;
            int gc = colBase + c;
            if (gc < NC) {
                float v = Cs[r * C_LD + c];
                if (HASB) v += bias[gc];
                Cout[(size_t)(rowBase + r) * NC + gc] = v;
            }
        }
    }
}

// ============================================================
// Fused softmax + attention-apply + fold, phase-overlapped:
//   A) cp.async the fp16 v tile into smem (zfill OOB) -- background
//   B) w[25] from 81 logit loads + exp (overlaps A's copies)
//   C) wait + sync, then fp16-smem gather with fp32 accumulate
// smem: 20x20 pixels, stride 40 halves (80B = odd mult of 16B ->
// LDS.128 bank starts 20i mod 32: conflict-free). 32KB static.
// ============================================================
#define VSTH 40

__global__ void __launch_bounds__(256) agg_kernel(const __half* __restrict__ a,
                                                  const __half* __restrict__ v,
                                                  __half* __restrict__ o)
{
    __shared__ __align__(16) __half vsm[20 * 20 * VSTH];   // 32 KB

    const int bh = blockIdx.z;
    const int b  = bh / HEADS;
    const int h  = bh - b * HEADS;
    const int ty0 = blockIdx.y * 16;
    const int tx0 = blockIdx.x * 16;
    const int tid = threadIdx.x;

    // Phase A: async fp16 v-tile fill (400 px * 4 x 16B chunks)
    for (int i = tid; i < 20 * 20 * 4; i += 256) {
        int p = i >> 2;
        int q = (i & 3) << 3;                  // halves offset within pixel
        int sy = p / 20;
        int sx = p - sy * 20;
        int gy = ty0 + sy - 2;
        int gx = tx0 + sx - 2;
        bool ok = (gy >= 0 && gy < HH && gx >= 0 && gx < WW);
        const __half* src = ok
            ? &v[((size_t)(b * HW + gy * WW + gx)) * CC + h * HEAD_DIM + q]
            : v;                               // valid dummy address, 0 bytes read
        uint32_t d = (uint32_t)__cvta_generic_to_shared(&vsm[p * VSTH + q]);
        int sz = ok ? 16 : 0;                  // zfill OOB pixels
        asm volatile("cp.async.cg.shared.global [%0], [%1], 16, %2;\n"
                     :: "r"(d), "l"(src), "r"(sz));
    }
    asm volatile("cp.async.commit_group;\n");

    const int px = tid & 15;
    const int py = tid >> 4;
    const int gy = ty0 + py;
    const int gx = tx0 + px;
    const bool active = (gy < HH) && (gx < WW);

    // Phase B: 81 logit loads + exp + reduce to 25 weights (overlaps A)
    float w[25];
#pragma unroll
    for (int i = 0; i < 25; i++) w[i] = 0.f;

    if (active) {
#pragma unroll
        for (int i = 0; i < 3; i++) {
#pragma unroll
            for (int j = 0; j < 3; j++) {
                const int cy = gy + 1 - i;
                const int cx = gx + 1 - j;
                if (cy < 0 || cy >= HH || cx < 0 || cx >= WW) continue;
                const size_t row = (size_t)(b * HW + cy * WW + cx);
                const __half* ap = a + (size_t)(h * 81 + (i * 3 + j) * 9) * NROWS + row;
                float e[9];
                float s = 0.f;
                // logits pre-scaled, |arg| small: exp safe without max-shift
#pragma unroll
                for (int l = 0; l < 9; l++) {
                    e[l] = __expf(__half2float(ap[(size_t)l * NROWS]));
                    s += e[l];
                }
                const float inv = 1.f / s;
#pragma unroll
                for (int li = 0; li < 3; li++) {
#pragma unroll
                    for (int lj = 0; lj < 3; lj++) {
                        w[(li - i + 2) * 5 + (lj - j + 2)] += e[li * 3 + lj] * inv;
                    }
                }
            }
        }
    }

    // Phase C: wait for v tile, then gather
    asm volatile("cp.async.wait_group 0;\n" ::: "memory");
    __syncthreads();

    if (!active) return;

    float acc[HEAD_DIM];
#pragma unroll
    for (int d = 0; d < HEAD_DIM; d++) acc[d] = 0.f;

#pragma unroll
    for (int dy = 0; dy < 5; dy++) {
#pragma unroll
        for (int dx = 0; dx < 5; dx++) {
            const float wv = w[dy * 5 + dx];
            const __half* vp = &vsm[((py + dy) * 20 + (px + dx)) * VSTH];
#pragma unroll
            for (int u = 0; u < 4; u++) {      // 4 x LDS.128 (8 halves each)
                uint4 t = *(const uint4*)(vp + u * 8);
                float2 f0 = __half22float2(*(const __half2*)&t.x);
                float2 f1 = __half22float2(*(const __half2*)&t.y);
                float2 f2 = __half22float2(*(const __half2*)&t.z);
                float2 f3 = __half22float2(*(const __half2*)&t.w);
                acc[u * 8 + 0] += wv * f0.x;
                acc[u * 8 + 1] += wv * f0.y;
                acc[u * 8 + 2] += wv * f1.x;
                acc[u * 8 + 3] += wv * f1.y;
                acc[u * 8 + 4] += wv * f2.x;
                acc[u * 8 + 5] += wv * f2.y;
                acc[u * 8 + 6] += wv * f3.x;
                acc[u * 8 + 7] += wv * f3.y;
            }
        }
    }

    __half2* op = (__half2*)(o + ((size_t)(b * HW + gy * WW + gx)) * CC + h * HEAD_DIM);
#pragma unroll
    for (int u = 0; u < HEAD_DIM / 2; u++)
        op[u] = __floats2half2_rn(acc[2 * u], acc[2 * u + 1]);
}

// ============================================================
extern "C" void kernel_launch(void* const* d_in, const int* in_sizes, int n_in,
                              void* d_out, int out_size)
{
    const float* x  = (const float*)d_in[0];
    const float* Wv = (const float*)d_in[1];
    const float* Wa = (const float*)d_in[2];
    const float* ba = (const float*)d_in[3];
    const float* Wp = (const float*)d_in[4];
    const float* bp = (const float*)d_in[5];
    float* out = (float*)d_out;

    __half *x16, *wv16, *wa16, *wp16, *v16, *a16, *o16;
    cudaGetSymbolAddress((void**)&x16,  g_x16);
    cudaGetSymbolAddress((void**)&wv16, g_wv16);
    cudaGetSymbolAddress((void**)&wa16, g_wa16);
    cudaGetSymbolAddress((void**)&wp16, g_wp16);
    cudaGetSymbolAddress((void**)&v16,  g_v16);
    cudaGetSymbolAddress((void**)&a16,  g_a16);
    cudaGetSymbolAddress((void**)&o16,  g_o16);

    // 0) all conversions in one launch
    cvt_all<<<(CVT_TOT + 255) / 256, 256>>>(x, Wv, Wp, Wa, x16, wv16, wp16, (__half2*)wa16);

    // 1) v16 = x @ Wv   (fp16 out)
    gemm_h<192, 192, false, false, true>
        <<<dim3(3, NROWS / BM), 256>>>(x16, wv16, nullptr, v16);
    // 2) a16_t = transpose((x @ Wa + ba) * SCALE)   (fp16, column-major)
    gemm_h<NAPAD, NA, true, true, false>
        <<<dim3(NAPAD / BN, NROWS / BM), 256>>>(x16, wa16, ba, a16);
    // 3) fused softmax + attention-apply + fold  (o fp16)
    agg_kernel<<<dim3(4, 4, BB * HEADS), 256>>>(a16, v16, o16);
    // 4) out = o @ Wp + bp   (fp32 out)
    gemm_h<192, 192, true, false, false>
        <<<dim3(3, NROWS / BM), 256>>>(o16, wp16, bp, out);
}